// round 13
// baseline (speedup 1.0000x reference)
#include <cuda_runtime.h>
#include <cuda_bf16.h>
#include <cstdint>
#include <math.h>

#define BATCH 8192
#define NCVS  4096
#define FEAT  128
#define KNN   15
#define CMAX  512   // candidate buffer
#define RPB   2     // topk rows per block (restores MLP=16 with bf16 stream)

// ---------------- static scratch ----------------
__device__ __nv_bfloat16 g_d2b[(size_t)BATCH * NCVS];  // approx distances bf16 (64 MB)
__device__ int    g_cce[(size_t)NCVS * NCVS];    // self-cleaning via undo
__device__ int    g_nlist[(size_t)NCVS * NCVS];  // per-label neighbor lists
__device__ int    g_ncnt[NCVS];
__device__ int    g_visits[NCVS];                // self-cleaning
__device__ int    g_knn[BATCH * KNN];
__device__ float  g_xx[BATCH];
__device__ float  g_cc[NCVS];
__device__ double g_loss;                        // self-cleaning
__device__ __nv_bfloat16 g_xb[(size_t)BATCH * FEAT];
__device__ __nv_bfloat16 g_cb[(size_t)NCVS  * FEAT];

// ---------------- K0: convert f32 -> bf16 ----------------
__global__ void split_kernel(const float* __restrict__ X, const float* __restrict__ C) {
    int i  = blockIdx.x * blockDim.x + threadIdx.x;
    int nx = BATCH * FEAT;
    if (i < nx) {
        g_xb[i] = __float2bfloat16(X[i]);
    } else {
        int j = i - nx;
        if (j < NCVS * FEAT) g_cb[j] = __float2bfloat16(C[j]);
    }
}

// ---------------- K1: row squared norms ----------------
__global__ void norms_kernel(const float* __restrict__ X, const float* __restrict__ C) {
    int warp = (blockIdx.x * blockDim.x + threadIdx.x) >> 5;
    int lane = threadIdx.x & 31;
    if (warp < BATCH) {
        const float* r = X + (size_t)warp * FEAT;
        float s = 0.f;
        #pragma unroll
        for (int i = 0; i < 4; i++) { float v = r[lane + 32 * i]; s += v * v; }
        #pragma unroll
        for (int o = 16; o; o >>= 1) s += __shfl_down_sync(0xffffffffu, s, o);
        if (lane == 0) g_xx[warp] = s;
    } else if (warp < BATCH + NCVS) {
        int rr = warp - BATCH;
        const float* r = C + (size_t)rr * FEAT;
        float s = 0.f;
        #pragma unroll
        for (int i = 0; i < 4; i++) { float v = r[lane + 32 * i]; s += v * v; }
        #pragma unroll
        for (int o = 16; o; o >>= 1) s += __shfl_down_sync(0xffffffffu, s, o);
        if (lane == 0) g_cc[rr] = s;
    }
}

// ---------------- K2: bf16 mma.sync distance GEMM (bf16 epilogue) ----------------
#define SM_STRIDE 272
#define A_OFF 0
#define B_OFF (128 * SM_STRIDE)
#define GEMM_SMEM (2 * 128 * SM_STRIDE)

__device__ __forceinline__ uint32_t smem_u32(const void* p) {
    uint32_t a;
    asm("{ .reg .u64 t; cvta.to.shared.u64 t, %1; cvt.u32.u64 %0, t; }" : "=r"(a) : "l"(p));
    return a;
}
#define LDMX4(r0, r1, r2, r3, addr) \
    asm volatile("ldmatrix.sync.aligned.m8n8.x4.shared.b16 {%0,%1,%2,%3}, [%4];" \
                 : "=r"(r0), "=r"(r1), "=r"(r2), "=r"(r3) : "r"(addr))
#define MMA16816(c, a, b0, b1) \
    asm volatile("mma.sync.aligned.m16n8k16.row.col.f32.bf16.bf16.f32 " \
                 "{%0,%1,%2,%3}, {%4,%5,%6,%7}, {%8,%9}, {%0,%1,%2,%3};" \
                 : "+f"((c)[0]), "+f"((c)[1]), "+f"((c)[2]), "+f"((c)[3]) \
                 : "r"((a)[0]), "r"((a)[1]), "r"((a)[2]), "r"((a)[3]), "r"(b0), "r"(b1))

__global__ __launch_bounds__(256, 2) void gemm_tc_kernel() {
    extern __shared__ char dsm[];
    const int tid  = threadIdx.x;
    const int lane = tid & 31;
    const int w    = tid >> 5;
    const int bm   = blockIdx.y * 128;
    const int bn   = blockIdx.x * 128;
    const int wm   = (w & 3) * 32;
    const int wn   = (w >> 2) * 64;

    {
        const __nv_bfloat16* Asrc = g_xb + (size_t)bm * FEAT;
        const __nv_bfloat16* Bsrc = g_cb + (size_t)bn * FEAT;
        #pragma unroll
        for (int i = 0; i < 8; i++) {
            int idx = tid + i * 256;
            int r = idx >> 4, q = idx & 15;
            *(uint4*)(dsm + A_OFF + r * SM_STRIDE + q * 16) =
                *(const uint4*)(Asrc + (size_t)r * FEAT + q * 8);
            *(uint4*)(dsm + B_OFF + r * SM_STRIDE + q * 16) =
                *(const uint4*)(Bsrc + (size_t)r * FEAT + q * 8);
        }
    }
    __syncthreads();

    const uint32_t asb = smem_u32(dsm + A_OFF);
    const uint32_t bsb = smem_u32(dsm + B_OFF);
    const int tile = lane >> 3, rin = lane & 7;

    uint32_t aaddr[2], baddr[4];
    #pragma unroll
    for (int sm = 0; sm < 2; sm++)
        aaddr[sm] = asb + (uint32_t)((wm + sm * 16 + (tile & 1) * 8 + rin) * SM_STRIDE + (tile >> 1) * 16);
    #pragma unroll
    for (int np = 0; np < 4; np++)
        baddr[np] = bsb + (uint32_t)((wn + np * 16 + (tile & 1) * 8 + rin) * SM_STRIDE + (tile >> 1) * 16);

    float acc[2][8][4];
    #pragma unroll
    for (int s = 0; s < 2; s++)
        #pragma unroll
        for (int n = 0; n < 8; n++)
            #pragma unroll
            for (int q = 0; q < 4; q++) acc[s][n][q] = 0.f;

    #pragma unroll
    for (int ks = 0; ks < 8; ks++) {
        uint32_t a[2][4], bfr[4][4];
        LDMX4(a[0][0], a[0][1], a[0][2], a[0][3], aaddr[0] + ks * 32);
        LDMX4(a[1][0], a[1][1], a[1][2], a[1][3], aaddr[1] + ks * 32);
        #pragma unroll
        for (int np = 0; np < 4; np++)
            LDMX4(bfr[np][0], bfr[np][1], bfr[np][2], bfr[np][3], baddr[np] + ks * 32);
        #pragma unroll
        for (int s = 0; s < 2; s++)
            #pragma unroll
            for (int nt = 0; nt < 8; nt++) {
                int np = nt >> 1, odd = nt & 1;
                uint32_t b0 = odd ? bfr[np][1] : bfr[np][0];
                uint32_t b1 = odd ? bfr[np][3] : bfr[np][2];
                MMA16816(acc[s][nt], a[s], b0, b1);
            }
    }

    // epilogue: d2 = xx + cc - 2*dot, clamp >= 0, bf16 store (64 MB)
    const int cb = bn + wn + (lane & 3) * 2;
    #pragma unroll
    for (int s = 0; s < 2; s++) {
        int m0 = bm + wm + s * 16 + (lane >> 2);
        float xx0 = g_xx[m0], xx1 = g_xx[m0 + 8];
        __nv_bfloat16* row0 = g_d2b + (size_t)m0 * NCVS;
        __nv_bfloat16* row1 = g_d2b + (size_t)(m0 + 8) * NCVS;
        #pragma unroll
        for (int nt = 0; nt < 8; nt++) {
            int c = cb + nt * 8;
            float2 cc2 = *(const float2*)(g_cc + c);
            float2 o0, o1;
            o0.x = fmaxf(xx0 + cc2.x - 2.0f * acc[s][nt][0], 0.0f);
            o0.y = fmaxf(xx0 + cc2.y - 2.0f * acc[s][nt][1], 0.0f);
            o1.x = fmaxf(xx1 + cc2.x - 2.0f * acc[s][nt][2], 0.0f);
            o1.y = fmaxf(xx1 + cc2.y - 2.0f * acc[s][nt][3], 0.0f);
            *(__nv_bfloat162*)(row0 + c) = __float22bfloat162_rn(o0);
            *(__nv_bfloat162*)(row1 + c) = __float22bfloat162_rn(o1);
        }
    }
}

// ---------------- K3: 2-row topk (bf16 stream, 16 strided LDG.32/thread) ------------
// MLP law (R11 vs R12): achieved BW ~ outstanding lines/thread. 2 rows/block
// restores 16 independent strided LDG.32 per thread on the bf16 (64 MB) stream.
// Filter: {j : d2_j < m + d + 4.0}, count(d2 < m+d) >= 15; err budget: GEMM ~0.6
// + bf16 store round <=1.0 => 2*err ~3.2 < 4.0. Rescore: warp-per-candidate
// coalesced exact f32 dot. Select: rank over exact lex keys (value,index).
__global__ __launch_bounds__(256) void topk_kernel(const float* __restrict__ X,
                                                   const float* __restrict__ C) {
    __shared__ float    s_red[8];
    __shared__ unsigned s_c12[8], s_c34[8];
    __shared__ int      s_icnt[8];
    __shared__ int      s_cnt;
    __shared__ int      s_cand[CMAX];
    __shared__ float    s_ed[CMAX];
    __shared__ int      s_knn[KNN];

    const int tid  = threadIdx.x;
    const int lane = tid & 31, w = tid >> 5;
    const int row0 = blockIdx.x * RPB;
    const int wword = w * 256;   // word base within row (2 bf16/word)

    // front-load BOTH rows: 16 independent strided LDG.32 (proven MLP shape)
    uint32_t u[RPB][8];
    #pragma unroll
    for (int r = 0; r < RPB; r++) {
        const uint32_t* drow = (const uint32_t*)(g_d2b + (size_t)(row0 + r) * NCVS);
        #pragma unroll
        for (int i = 0; i < 8; i++) u[r][i] = drow[wword + i * 32 + lane];
    }

    #pragma unroll 1
    for (int r = 0; r < RPB; r++) {
        const int row = row0 + r;

        float v[16];
        #pragma unroll
        for (int i = 0; i < 8; i++) {
            v[i * 2]     = __uint_as_float(u[r][i] << 16);          // low bf16 (exact)
            v[i * 2 + 1] = __uint_as_float(u[r][i] & 0xFFFF0000u);  // high bf16 (exact)
        }

        // block min
        float mn = v[0];
        #pragma unroll
        for (int i = 1; i < 16; i++) mn = fminf(mn, v[i]);
        #pragma unroll
        for (int o = 16; o; o >>= 1) mn = fminf(mn, __shfl_xor_sync(0xffffffffu, mn, o));
        if (lane == 0) s_red[w] = mn;
        if (tid == 0) s_cnt = 0;
        __syncthreads();
        float m = s_red[0];
        #pragma unroll
        for (int p = 1; p < 8; p++) m = fminf(m, s_red[p]);

        // single-pass 4-threshold count: d in {4,8,16,32}, packed 2x16-bit
        {
            float T1 = m + 4.0f, T2 = m + 8.0f, T3 = m + 16.0f, T4 = m + 32.0f;
            unsigned c12 = 0, c34 = 0;
            #pragma unroll
            for (int i = 0; i < 16; i++) {
                c12 += (v[i] < T1 ? 1u : 0u) + (v[i] < T2 ? 0x10000u : 0u);
                c34 += (v[i] < T3 ? 1u : 0u) + (v[i] < T4 ? 0x10000u : 0u);
            }
            c12 = __reduce_add_sync(0xffffffffu, c12);
            c34 = __reduce_add_sync(0xffffffffu, c34);
            if (lane == 0) { s_c12[w] = c12; s_c34[w] = c34; }
        }
        __syncthreads();
        unsigned t12 = 0, t34 = 0;
        #pragma unroll
        for (int p = 0; p < 8; p++) { t12 += s_c12[p]; t34 += s_c34[p]; }
        int n1 = (int)(t12 & 0xFFFFu), n2 = (int)(t12 >> 16);
        int n3 = (int)(t34 & 0xFFFFu), n4 = (int)(t34 >> 16);

        float d;
        if      (n1 >= KNN) d = 4.0f;
        else if (n2 >= KNN) d = 8.0f;
        else if (n3 >= KNN) d = 16.0f;
        else if (n4 >= KNN) d = 32.0f;
        else {
            d = 64.0f;   // rare fallback: doubling
            for (int iter = 0; iter < 20; iter++) {
                float T0 = m + d;
                unsigned c = 0;
                #pragma unroll
                for (int i = 0; i < 16; i++) c += (v[i] < T0) ? 1u : 0u;
                c = __reduce_add_sync(0xffffffffu, c);
                if (lane == 0) s_icnt[w] = (int)c;
                __syncthreads();
                int total = 0;
                #pragma unroll
                for (int p = 0; p < 8; p++) total += s_icnt[p];
                if (total >= KNN) break;
                d *= 2.0f;
                __syncthreads();
            }
        }
        const float T = m + d + 4.0f;

        // compact candidate indices (set; order irrelevant)
        #pragma unroll
        for (int i = 0; i < 16; i++) {
            if (v[i] < T) {
                int p = atomicAdd(&s_cnt, 1);
                if (p < CMAX)
                    s_cand[p] = 2 * (wword + (i >> 1) * 32 + lane) + (i & 1);
            }
        }
        __syncthreads();
        const int M = (s_cnt < CMAX) ? s_cnt : CMAX;

        // exact f32 rescore: warp-per-candidate, coalesced (proven)
        {
            float4 xq = *(const float4*)(X + (size_t)row * FEAT + lane * 4);
            float xxv = g_xx[row];
            for (int c = w; c < M; c += 8) {
                int j = s_cand[c];
                float4 cq = *(const float4*)(C + (size_t)j * FEAT + lane * 4);
                float p = xq.x * cq.x + xq.y * cq.y + xq.z * cq.z + xq.w * cq.w;
                #pragma unroll
                for (int o = 16; o; o >>= 1) p += __shfl_down_sync(0xffffffffu, p, o);
                if (lane == 0) s_ed[c] = fmaxf(xxv + g_cc[j] - 2.0f * p, 0.0f);
            }
        }
        __syncthreads();

        // rank-based select: rank_c = #{keys < key_c}; rank < 15 writes knn[rank]
        for (int c = tid; c < M; c += 256) {
            unsigned long long key =
                ((unsigned long long)__float_as_uint(s_ed[c]) << 32) | (unsigned)s_cand[c];
            int rank = 0;
            for (int jj = 0; jj < M; jj++) {
                unsigned long long kj =
                    ((unsigned long long)__float_as_uint(s_ed[jj]) << 32) | (unsigned)s_cand[jj];
                rank += (kj < key) ? 1 : 0;
            }
            if (rank < KNN) {
                s_knn[rank] = s_cand[c];
                g_knn[row * KNN + rank] = s_cand[c];
            }
        }
        __syncthreads();

        // fused scatter
        if (w == 0) {
            int closest = s_knn[0];
            if (lane == 0) atomicAdd(&g_visits[closest], 1);
            if (lane < KNN) atomicAdd(&g_cce[(size_t)closest * NCVS + s_knn[lane]], 1);
        }
        __syncthreads();   // protect shared state before next row
    }
}

// ---------------- K4: build per-label neighbor lists (vectorized) ----------------
// (0.9f)^10 < f32(double(0.9^10)) so integer-edge rows keep enc <= 9 only.
__global__ void build_kernel(const float* __restrict__ edges, const float* __restrict__ conn) {
    __shared__ int s_scan[256];
    const int lab = blockIdx.x;
    const int tid = threadIdx.x;
    float vis = (float)g_visits[lab];
    const int4*   ccer = (const int4*)  (g_cce + (size_t)lab * NCVS);
    const float4* er   = (const float4*)(edges + (size_t)lab * NCVS);
    const float4* cor  = (const float4*)(conn  + (size_t)lab * NCVS);

    unsigned mask = 0;
    #pragma unroll
    for (int it = 0; it < 4; it++) {
        int g = tid + (it << 8);
        int4   c4 = ccer[g];
        float4 e4 = er[g];
        float4 o4 = cor[g];
        int    cc[4] = {c4.x, c4.y, c4.z, c4.w};
        float  ee[4] = {e4.x, e4.y, e4.z, e4.w};
        float  oo[4] = {o4.x, o4.y, o4.z, o4.w};
        #pragma unroll
        for (int q = 0; q < 4; q++) {
            bool keep = false;
            if (cc[q] > 0 || ee[q] > 0.f) {
                float base = fmaxf(ee[q], (cc[q] > 0) ? 1.0f : 0.0f);
                float enc  = fmaxf(vis - (float)cc[q], 0.0f);
                if (base >= 1.0f) keep = (enc < 9.5f);
                else {
                    float en = base * __powf(0.89999997615814209f, enc);
                    keep = !(en < 0.34867844358f);
                }
                keep = keep && (oo[q] < 1.0f);
            }
            if (keep) mask |= (1u << (it * 4 + q));
        }
    }
    int cnt = __popc(mask);
    s_scan[tid] = cnt;
    __syncthreads();
    for (int off = 1; off < 256; off <<= 1) {
        int vv = (tid >= off) ? s_scan[tid - off] : 0;
        __syncthreads();
        s_scan[tid] += vv;
        __syncthreads();
    }
    int pos = s_scan[tid] - cnt;
    int* dst = g_nlist + (size_t)lab * NCVS;
    #pragma unroll
    for (int b = 0; b < 16; b++)
        if (mask & (1u << b)) dst[pos++] = 4 * (tid + ((b >> 2) << 8)) + (b & 3);
    if (tid == 255) g_ncnt[lab] = s_scan[255];
}

// ---------------- K5: per-sample loss, exact f32 neighbor distances ----------------
__global__ void loss_kernel(const float* __restrict__ X, const float* __restrict__ C,
                            const int* __restrict__ labels) {
    __shared__ float s_dp[4], s_se[4], s_sed[4];
    const int b    = blockIdx.x;
    const int tid  = threadIdx.x;
    const int lane = tid & 31, wid = tid >> 5;
    const int lab  = labels[b];

    const float* xr = X + (size_t)b   * FEAT;
    const float* cr = C + (size_t)lab * FEAT;
    float dlt = xr[tid] - cr[tid];
    float dp  = dlt * dlt;
    #pragma unroll
    for (int o = 16; o; o >>= 1) dp += __shfl_down_sync(0xffffffffu, dp, o);

    const int  L  = g_ncnt[lab];
    const int* nl = g_nlist + (size_t)lab * NCVS;
    const float xxv = g_xx[b];
    float4 xq = *(const float4*)(xr + lane * 4);

    float se = 0.f, sed = 0.f;
    for (int k = wid; k < L; k += 4) {
        int j = nl[k];
        float4 cq = *(const float4*)(C + (size_t)j * FEAT + lane * 4);
        float p = xq.x * cq.x + xq.y * cq.y + xq.z * cq.z + xq.w * cq.w;
        #pragma unroll
        for (int o = 16; o; o >>= 1) p += __shfl_down_sync(0xffffffffu, p, o);
        if (lane == 0) {
            float dd = fmaxf(xxv + g_cc[j] - 2.0f * p, 0.0f);
            if (dd > 0.f) {
                float ex = expf(-0.001f * dd);
                se  += ex;
                sed += ex * dd;
            }
        }
    }

    if (lane == 0) { s_dp[wid] = dp; s_se[wid] = se; s_sed[wid] = sed; }
    __syncthreads();
    if (tid == 0) {
        float dpt  = s_dp[0]  + s_dp[1]  + s_dp[2]  + s_dp[3];
        float set  = s_se[0]  + s_se[1]  + s_se[2]  + s_se[3];
        float sedt = s_sed[0] + s_sed[1] + s_sed[2] + s_sed[3];
        float wsum = (set > 0.f) ? (sedt / set) : 0.f;   // nan -> 0 branch
        float mu = dpt - wsum;
        if (mu > 0.f) atomicAdd(&g_loss, (double)mu);
    }
}

// ---------------- K6: finalize ----------------
__global__ void finalize_kernel(float* out) {
    if (threadIdx.x == 0) out[0] = (float)(g_loss * (1.0 / (double)BATCH));
}

// ---------------- K7: undo scatter (self-cleaning state) ----------------
__global__ void undo_kernel() {
    int b = blockIdx.x * blockDim.x + threadIdx.x;
    if (b == 0) g_loss = 0.0;
    if (b >= BATCH) return;
    int closest = g_knn[b * KNN];
    atomicSub(&g_visits[closest], 1);
    #pragma unroll
    for (int k = 0; k < KNN; k++)
        atomicSub(&g_cce[(size_t)closest * NCVS + g_knn[b * KNN + k]], 1);
}

// ---------------- launch ----------------
extern "C" void kernel_launch(void* const* d_in, const int* in_sizes, int n_in,
                              void* d_out, int out_size) {
    const float* x      = (const float*)d_in[0];
    const float* cvs    = (const float*)d_in[1];
    const float* edges  = (const float*)d_in[2];
    const float* conn   = (const float*)d_in[3];
    const int*   labels = (const int*)d_in[4];
    float* out = (float*)d_out;

    cudaFuncSetAttribute(gemm_tc_kernel, cudaFuncAttributeMaxDynamicSharedMemorySize, GEMM_SMEM);

    split_kernel<<<(BATCH + NCVS) * FEAT / 256, 256>>>(x, cvs);
    norms_kernel<<<(BATCH + NCVS) / 8, 256>>>(x, cvs);
    gemm_tc_kernel<<<dim3(NCVS / 128, BATCH / 128), 256, GEMM_SMEM>>>();
    topk_kernel<<<BATCH / RPB, 256>>>(x, cvs);
    build_kernel<<<NCVS, 256>>>(edges, conn);
    loss_kernel<<<BATCH, 128>>>(x, cvs, labels);
    finalize_kernel<<<1, 32>>>(out);
    undo_kernel<<<BATCH / 256, 256>>>();
}

// round 14
// speedup vs baseline: 2.1489x; 2.1489x over previous
#include <cuda_runtime.h>
#include <cuda_bf16.h>
#include <cstdint>
#include <math.h>

#define BATCH 8192
#define NCVS  4096
#define FEAT  128
#define KNN   15
#define CMAX  512   // candidate buffer
#define NTILE 128   // 32-col tiles per row

// ---------------- static scratch ----------------
__device__ float  g_d2[(size_t)BATCH * NCVS];    // approx distances f32 (128 MB)
__device__ float  g_tmin[(size_t)BATCH * NTILE]; // per-32-col tile minima (4 MB)
__device__ int    g_cce[(size_t)NCVS * NCVS];    // self-cleaning via undo
__device__ int    g_nlist[(size_t)NCVS * NCVS];  // per-label neighbor lists
__device__ int    g_ncnt[NCVS];
__device__ int    g_visits[NCVS];                // self-cleaning
__device__ int    g_knn[BATCH * KNN];
__device__ float  g_xx[BATCH];
__device__ float  g_cc[NCVS];
__device__ double g_loss;                        // self-cleaning
__device__ __nv_bfloat16 g_xb[(size_t)BATCH * FEAT];
__device__ __nv_bfloat16 g_cb[(size_t)NCVS  * FEAT];

// ---------------- K0: convert f32 -> bf16 ----------------
__global__ void split_kernel(const float* __restrict__ X, const float* __restrict__ C) {
    int i  = blockIdx.x * blockDim.x + threadIdx.x;
    int nx = BATCH * FEAT;
    if (i < nx) {
        g_xb[i] = __float2bfloat16(X[i]);
    } else {
        int j = i - nx;
        if (j < NCVS * FEAT) g_cb[j] = __float2bfloat16(C[j]);
    }
}

// ---------------- K1: row squared norms ----------------
__global__ void norms_kernel(const float* __restrict__ X, const float* __restrict__ C) {
    int warp = (blockIdx.x * blockDim.x + threadIdx.x) >> 5;
    int lane = threadIdx.x & 31;
    if (warp < BATCH) {
        const float* r = X + (size_t)warp * FEAT;
        float s = 0.f;
        #pragma unroll
        for (int i = 0; i < 4; i++) { float v = r[lane + 32 * i]; s += v * v; }
        #pragma unroll
        for (int o = 16; o; o >>= 1) s += __shfl_down_sync(0xffffffffu, s, o);
        if (lane == 0) g_xx[warp] = s;
    } else if (warp < BATCH + NCVS) {
        int rr = warp - BATCH;
        const float* r = C + (size_t)rr * FEAT;
        float s = 0.f;
        #pragma unroll
        for (int i = 0; i < 4; i++) { float v = r[lane + 32 * i]; s += v * v; }
        #pragma unroll
        for (int o = 16; o; o >>= 1) s += __shfl_down_sync(0xffffffffu, s, o);
        if (lane == 0) g_cc[rr] = s;
    }
}

// ---------------- K2: bf16 mma.sync distance GEMM + tile-min epilogue ----------------
#define SM_STRIDE 272
#define A_OFF 0
#define B_OFF (128 * SM_STRIDE)
#define GEMM_SMEM (2 * 128 * SM_STRIDE)

__device__ __forceinline__ uint32_t smem_u32(const void* p) {
    uint32_t a;
    asm("{ .reg .u64 t; cvta.to.shared.u64 t, %1; cvt.u32.u64 %0, t; }" : "=r"(a) : "l"(p));
    return a;
}
#define LDMX4(r0, r1, r2, r3, addr) \
    asm volatile("ldmatrix.sync.aligned.m8n8.x4.shared.b16 {%0,%1,%2,%3}, [%4];" \
                 : "=r"(r0), "=r"(r1), "=r"(r2), "=r"(r3) : "r"(addr))
#define MMA16816(c, a, b0, b1) \
    asm volatile("mma.sync.aligned.m16n8k16.row.col.f32.bf16.bf16.f32 " \
                 "{%0,%1,%2,%3}, {%4,%5,%6,%7}, {%8,%9}, {%0,%1,%2,%3};" \
                 : "+f"((c)[0]), "+f"((c)[1]), "+f"((c)[2]), "+f"((c)[3]) \
                 : "r"((a)[0]), "r"((a)[1]), "r"((a)[2]), "r"((a)[3]), "r"(b0), "r"(b1))

__global__ __launch_bounds__(256, 2) void gemm_tc_kernel() {
    extern __shared__ char dsm[];
    const int tid  = threadIdx.x;
    const int lane = tid & 31;
    const int w    = tid >> 5;
    const int bm   = blockIdx.y * 128;
    const int bn   = blockIdx.x * 128;
    const int wm   = (w & 3) * 32;
    const int wn   = (w >> 2) * 64;

    {
        const __nv_bfloat16* Asrc = g_xb + (size_t)bm * FEAT;
        const __nv_bfloat16* Bsrc = g_cb + (size_t)bn * FEAT;
        #pragma unroll
        for (int i = 0; i < 8; i++) {
            int idx = tid + i * 256;
            int r = idx >> 4, q = idx & 15;
            *(uint4*)(dsm + A_OFF + r * SM_STRIDE + q * 16) =
                *(const uint4*)(Asrc + (size_t)r * FEAT + q * 8);
            *(uint4*)(dsm + B_OFF + r * SM_STRIDE + q * 16) =
                *(const uint4*)(Bsrc + (size_t)r * FEAT + q * 8);
        }
    }
    __syncthreads();

    const uint32_t asb = smem_u32(dsm + A_OFF);
    const uint32_t bsb = smem_u32(dsm + B_OFF);
    const int tile = lane >> 3, rin = lane & 7;

    uint32_t aaddr[2], baddr[4];
    #pragma unroll
    for (int sm = 0; sm < 2; sm++)
        aaddr[sm] = asb + (uint32_t)((wm + sm * 16 + (tile & 1) * 8 + rin) * SM_STRIDE + (tile >> 1) * 16);
    #pragma unroll
    for (int np = 0; np < 4; np++)
        baddr[np] = bsb + (uint32_t)((wn + np * 16 + (tile & 1) * 8 + rin) * SM_STRIDE + (tile >> 1) * 16);

    float acc[2][8][4];
    #pragma unroll
    for (int s = 0; s < 2; s++)
        #pragma unroll
        for (int n = 0; n < 8; n++)
            #pragma unroll
            for (int q = 0; q < 4; q++) acc[s][n][q] = 0.f;

    #pragma unroll
    for (int ks = 0; ks < 8; ks++) {
        uint32_t a[2][4], bfr[4][4];
        LDMX4(a[0][0], a[0][1], a[0][2], a[0][3], aaddr[0] + ks * 32);
        LDMX4(a[1][0], a[1][1], a[1][2], a[1][3], aaddr[1] + ks * 32);
        #pragma unroll
        for (int np = 0; np < 4; np++)
            LDMX4(bfr[np][0], bfr[np][1], bfr[np][2], bfr[np][3], baddr[np] + ks * 32);
        #pragma unroll
        for (int s = 0; s < 2; s++)
            #pragma unroll
            for (int nt = 0; nt < 8; nt++) {
                int np = nt >> 1, odd = nt & 1;
                uint32_t b0 = odd ? bfr[np][1] : bfr[np][0];
                uint32_t b1 = odd ? bfr[np][3] : bfr[np][2];
                MMA16816(acc[s][nt], a[s], b0, b1);
            }
    }

    // epilogue: d2 = xx + cc - 2*dot, clamp >= 0, f32 store + per-32-col tile minima
    const int cb = bn + wn + (lane & 3) * 2;
    #pragma unroll
    for (int s = 0; s < 2; s++) {
        int m0 = bm + wm + s * 16 + (lane >> 2);
        float xx0 = g_xx[m0], xx1 = g_xx[m0 + 8];
        float* row0 = g_d2 + (size_t)m0 * NCVS;
        float* row1 = g_d2 + (size_t)(m0 + 8) * NCVS;
        float mn0[2] = {1e30f, 1e30f}, mn1[2] = {1e30f, 1e30f};
        #pragma unroll
        for (int nt = 0; nt < 8; nt++) {
            int c = cb + nt * 8;
            float2 cc2 = *(const float2*)(g_cc + c);
            float2 o0, o1;
            o0.x = fmaxf(xx0 + cc2.x - 2.0f * acc[s][nt][0], 0.0f);
            o0.y = fmaxf(xx0 + cc2.y - 2.0f * acc[s][nt][1], 0.0f);
            o1.x = fmaxf(xx1 + cc2.x - 2.0f * acc[s][nt][2], 0.0f);
            o1.y = fmaxf(xx1 + cc2.y - 2.0f * acc[s][nt][3], 0.0f);
            *(float2*)(row0 + c) = o0;
            *(float2*)(row1 + c) = o1;
            int t = nt >> 2;
            mn0[t] = fminf(mn0[t], fminf(o0.x, o0.y));
            mn1[t] = fminf(mn1[t], fminf(o1.x, o1.y));
        }
        #pragma unroll
        for (int t = 0; t < 2; t++) {
            mn0[t] = fminf(mn0[t], __shfl_xor_sync(0xffffffffu, mn0[t], 1));
            mn0[t] = fminf(mn0[t], __shfl_xor_sync(0xffffffffu, mn0[t], 2));
            mn1[t] = fminf(mn1[t], __shfl_xor_sync(0xffffffffu, mn1[t], 1));
            mn1[t] = fminf(mn1[t], __shfl_xor_sync(0xffffffffu, mn1[t], 2));
            if ((lane & 3) == 0) {
                int gt = ((bn + wn) >> 5) + t;
                g_tmin[(size_t)m0 * NTILE + gt]       = mn0[t];
                g_tmin[(size_t)(m0 + 8) * NTILE + gt] = mn1[t];
            }
        }
    }
}

// ---------------- K3: tile-min pruned topk + exact rescore + fused scatter ----------
// T15 = 15th-smallest tile-min (each tile-min IS a d2 value => >=15 candidates
// below T15+eps guaranteed). T = T15 + 2.0: exact top-15 j has approx_j <=
// exact_j + err <= (T15 + err) + err = T15 + 1.2 < T (err ~0.6, f32 d2). A
// candidate's tile has tmin <= approx_j < T, so tile pruning loses nothing.
// Then R11-proven warp-coalesced exact f32 rescore + rank select + scatter.
__global__ __launch_bounds__(256) void topk_kernel(const float* __restrict__ X,
                                                   const float* __restrict__ C) {
    __shared__ float s_tmin[NTILE];
    __shared__ float s_T;
    __shared__ int   s_qt[NTILE];
    __shared__ int   s_nqt;
    __shared__ int   s_cnt;
    __shared__ int   s_cand[CMAX];
    __shared__ float s_ed[CMAX];
    __shared__ int   s_knn[KNN];

    const int row  = blockIdx.x;
    const int tid  = threadIdx.x;
    const int lane = tid & 31, w = tid >> 5;

    if (tid == 0) { s_cnt = 0; s_nqt = 0; }
    if (tid < NTILE) s_tmin[tid] = g_tmin[(size_t)row * NTILE + tid];
    __syncthreads();

    // T15 = tile-min with rank 14 (lex tie-break by index => unique)
    if (tid < NTILE) {
        float mv = s_tmin[tid];
        int rank = 0;
        #pragma unroll 4
        for (int jj = 0; jj < NTILE; jj++) {
            float o = s_tmin[jj];
            rank += (o < mv || (o == mv && jj < tid)) ? 1 : 0;
        }
        if (rank == KNN - 1) s_T = mv;
    }
    __syncthreads();
    const float T = s_T + 2.0f;

    // qualifying tiles
    if (tid < NTILE && s_tmin[tid] < T) s_qt[atomicAdd(&s_nqt, 1)] = tid;
    __syncthreads();
    const int NQ = s_nqt;

    // scan qualifying tiles: warp per tile, 2 tiles in flight
    const float* drow = g_d2 + (size_t)row * NCVS;
    for (int q = w; q < NQ; q += 16) {
        int t0 = s_qt[q];
        int q1 = q + 8;
        int t1 = (q1 < NQ) ? s_qt[q1] : t0;
        float v0 = drow[t0 * 32 + lane];
        float v1 = drow[t1 * 32 + lane];
        if (v0 < T) {
            int p = atomicAdd(&s_cnt, 1);
            if (p < CMAX) s_cand[p] = t0 * 32 + lane;
        }
        if (q1 < NQ && v1 < T) {
            int p = atomicAdd(&s_cnt, 1);
            if (p < CMAX) s_cand[p] = t1 * 32 + lane;
        }
    }
    __syncthreads();
    const int M = (s_cnt < CMAX) ? s_cnt : CMAX;

    // exact f32 rescore: warp-per-candidate, coalesced (R11-proven)
    {
        float4 xq = *(const float4*)(X + (size_t)row * FEAT + lane * 4);
        float xxv = g_xx[row];
        for (int c = w; c < M; c += 8) {
            int j = s_cand[c];
            float4 cq = *(const float4*)(C + (size_t)j * FEAT + lane * 4);
            float p = xq.x * cq.x + xq.y * cq.y + xq.z * cq.z + xq.w * cq.w;
            #pragma unroll
            for (int o = 16; o; o >>= 1) p += __shfl_down_sync(0xffffffffu, p, o);
            if (lane == 0) s_ed[c] = fmaxf(xxv + g_cc[j] - 2.0f * p, 0.0f);
        }
    }
    __syncthreads();

    // rank-based select: rank_c = #{keys < key_c}; rank < 15 writes knn[rank]
    for (int c = tid; c < M; c += 256) {
        unsigned long long key =
            ((unsigned long long)__float_as_uint(s_ed[c]) << 32) | (unsigned)s_cand[c];
        int rank = 0;
        for (int jj = 0; jj < M; jj++) {
            unsigned long long kj =
                ((unsigned long long)__float_as_uint(s_ed[jj]) << 32) | (unsigned)s_cand[jj];
            rank += (kj < key) ? 1 : 0;
        }
        if (rank < KNN) {
            s_knn[rank] = s_cand[c];
            g_knn[row * KNN + rank] = s_cand[c];
        }
    }
    __syncthreads();

    // fused scatter
    if (w == 0) {
        int closest = s_knn[0];
        if (lane == 0) atomicAdd(&g_visits[closest], 1);
        if (lane < KNN) atomicAdd(&g_cce[(size_t)closest * NCVS + s_knn[lane]], 1);
    }
}

// ---------------- K4: build per-label neighbor lists (vectorized) ----------------
// (0.9f)^10 < f32(double(0.9^10)) so integer-edge rows keep enc <= 9 only.
__global__ void build_kernel(const float* __restrict__ edges, const float* __restrict__ conn) {
    __shared__ int s_scan[256];
    const int lab = blockIdx.x;
    const int tid = threadIdx.x;
    float vis = (float)g_visits[lab];
    const int4*   ccer = (const int4*)  (g_cce + (size_t)lab * NCVS);
    const float4* er   = (const float4*)(edges + (size_t)lab * NCVS);
    const float4* cor  = (const float4*)(conn  + (size_t)lab * NCVS);

    unsigned mask = 0;
    #pragma unroll
    for (int it = 0; it < 4; it++) {
        int g = tid + (it << 8);
        int4   c4 = ccer[g];
        float4 e4 = er[g];
        float4 o4 = cor[g];
        int    cc[4] = {c4.x, c4.y, c4.z, c4.w};
        float  ee[4] = {e4.x, e4.y, e4.z, e4.w};
        float  oo[4] = {o4.x, o4.y, o4.z, o4.w};
        #pragma unroll
        for (int q = 0; q < 4; q++) {
            bool keep = false;
            if (cc[q] > 0 || ee[q] > 0.f) {
                float base = fmaxf(ee[q], (cc[q] > 0) ? 1.0f : 0.0f);
                float enc  = fmaxf(vis - (float)cc[q], 0.0f);
                if (base >= 1.0f) keep = (enc < 9.5f);
                else {
                    float en = base * __powf(0.89999997615814209f, enc);
                    keep = !(en < 0.34867844358f);
                }
                keep = keep && (oo[q] < 1.0f);
            }
            if (keep) mask |= (1u << (it * 4 + q));
        }
    }
    int cnt = __popc(mask);
    s_scan[tid] = cnt;
    __syncthreads();
    for (int off = 1; off < 256; off <<= 1) {
        int vv = (tid >= off) ? s_scan[tid - off] : 0;
        __syncthreads();
        s_scan[tid] += vv;
        __syncthreads();
    }
    int pos = s_scan[tid] - cnt;
    int* dst = g_nlist + (size_t)lab * NCVS;
    #pragma unroll
    for (int b = 0; b < 16; b++)
        if (mask & (1u << b)) dst[pos++] = 4 * (tid + ((b >> 2) << 8)) + (b & 3);
    if (tid == 255) g_ncnt[lab] = s_scan[255];
}

// ---------------- K5: per-sample loss, exact f32 neighbor distances ----------------
__global__ void loss_kernel(const float* __restrict__ X, const float* __restrict__ C,
                            const int* __restrict__ labels) {
    __shared__ float s_dp[4], s_se[4], s_sed[4];
    const int b    = blockIdx.x;
    const int tid  = threadIdx.x;
    const int lane = tid & 31, wid = tid >> 5;
    const int lab  = labels[b];

    const float* xr = X + (size_t)b   * FEAT;
    const float* cr = C + (size_t)lab * FEAT;
    float dlt = xr[tid] - cr[tid];
    float dp  = dlt * dlt;
    #pragma unroll
    for (int o = 16; o; o >>= 1) dp += __shfl_down_sync(0xffffffffu, dp, o);

    const int  L  = g_ncnt[lab];
    const int* nl = g_nlist + (size_t)lab * NCVS;
    const float xxv = g_xx[b];
    float4 xq = *(const float4*)(xr + lane * 4);

    float se = 0.f, sed = 0.f;
    for (int k = wid; k < L; k += 4) {
        int j = nl[k];
        float4 cq = *(const float4*)(C + (size_t)j * FEAT + lane * 4);
        float p = xq.x * cq.x + xq.y * cq.y + xq.z * cq.z + xq.w * cq.w;
        #pragma unroll
        for (int o = 16; o; o >>= 1) p += __shfl_down_sync(0xffffffffu, p, o);
        if (lane == 0) {
            float dd = fmaxf(xxv + g_cc[j] - 2.0f * p, 0.0f);
            if (dd > 0.f) {
                float ex = expf(-0.001f * dd);
                se  += ex;
                sed += ex * dd;
            }
        }
    }

    if (lane == 0) { s_dp[wid] = dp; s_se[wid] = se; s_sed[wid] = sed; }
    __syncthreads();
    if (tid == 0) {
        float dpt  = s_dp[0]  + s_dp[1]  + s_dp[2]  + s_dp[3];
        float set  = s_se[0]  + s_se[1]  + s_se[2]  + s_se[3];
        float sedt = s_sed[0] + s_sed[1] + s_sed[2] + s_sed[3];
        float wsum = (set > 0.f) ? (sedt / set) : 0.f;   // nan -> 0 branch
        float mu = dpt - wsum;
        if (mu > 0.f) atomicAdd(&g_loss, (double)mu);
    }
}

// ---------------- K6: finalize ----------------
__global__ void finalize_kernel(float* out) {
    if (threadIdx.x == 0) out[0] = (float)(g_loss * (1.0 / (double)BATCH));
}

// ---------------- K7: undo scatter (self-cleaning state) ----------------
__global__ void undo_kernel() {
    int b = blockIdx.x * blockDim.x + threadIdx.x;
    if (b == 0) g_loss = 0.0;
    if (b >= BATCH) return;
    int closest = g_knn[b * KNN];
    atomicSub(&g_visits[closest], 1);
    #pragma unroll
    for (int k = 0; k < KNN; k++)
        atomicSub(&g_cce[(size_t)closest * NCVS + g_knn[b * KNN + k]], 1);
}

// ---------------- launch ----------------
extern "C" void kernel_launch(void* const* d_in, const int* in_sizes, int n_in,
                              void* d_out, int out_size) {
    const float* x      = (const float*)d_in[0];
    const float* cvs    = (const float*)d_in[1];
    const float* edges  = (const float*)d_in[2];
    const float* conn   = (const float*)d_in[3];
    const int*   labels = (const int*)d_in[4];
    float* out = (float*)d_out;

    cudaFuncSetAttribute(gemm_tc_kernel, cudaFuncAttributeMaxDynamicSharedMemorySize, GEMM_SMEM);

    split_kernel<<<(BATCH + NCVS) * FEAT / 256, 256>>>(x, cvs);
    norms_kernel<<<(BATCH + NCVS) / 8, 256>>>(x, cvs);
    gemm_tc_kernel<<<dim3(NCVS / 128, BATCH / 128), 256, GEMM_SMEM>>>();
    topk_kernel<<<BATCH, 256>>>(x, cvs);
    build_kernel<<<NCVS, 256>>>(edges, conn);
    loss_kernel<<<BATCH, 128>>>(x, cvs, labels);
    finalize_kernel<<<1, 32>>>(out);
    undo_kernel<<<BATCH / 256, 256>>>();
}

// round 16
// speedup vs baseline: 2.2163x; 1.0314x over previous
#include <cuda_runtime.h>
#include <cuda_bf16.h>
#include <cstdint>
#include <math.h>

#define BATCH 8192
#define NCVS  4096
#define FEAT  128
#define KNN   15
#define CMAX  512   // candidate buffer
#define NTILE 128   // 32-col tiles per row

// ---------------- static scratch ----------------
__device__ __nv_bfloat16 g_d2b[(size_t)BATCH * NCVS];  // approx distances bf16 (64 MB)
__device__ float  g_tmin[(size_t)BATCH * NTILE];       // per-32-col tile minima f32 (4 MB)
__device__ int    g_cce[(size_t)NCVS * NCVS];    // self-cleaning via undo
__device__ int    g_nlist[(size_t)NCVS * NCVS];  // per-label neighbor lists
__device__ int    g_ncnt[NCVS];
__device__ int    g_visits[NCVS];                // self-cleaning
__device__ int    g_knn[BATCH * KNN];
__device__ float  g_xx[BATCH];
__device__ float  g_cc[NCVS];
__device__ double g_loss;                        // self-cleaning
__device__ __nv_bfloat16 g_xb[(size_t)BATCH * FEAT];
__device__ __nv_bfloat16 g_cb[(size_t)NCVS  * FEAT];

// ---------------- K0: convert f32 -> bf16 ----------------
__global__ void split_kernel(const float* __restrict__ X, const float* __restrict__ C) {
    int i  = blockIdx.x * blockDim.x + threadIdx.x;
    int nx = BATCH * FEAT;
    if (i < nx) {
        g_xb[i] = __float2bfloat16(X[i]);
    } else {
        int j = i - nx;
        if (j < NCVS * FEAT) g_cb[j] = __float2bfloat16(C[j]);
    }
}

// ---------------- K1: row squared norms ----------------
__global__ void norms_kernel(const float* __restrict__ X, const float* __restrict__ C) {
    int warp = (blockIdx.x * blockDim.x + threadIdx.x) >> 5;
    int lane = threadIdx.x & 31;
    if (warp < BATCH) {
        const float* r = X + (size_t)warp * FEAT;
        float s = 0.f;
        #pragma unroll
        for (int i = 0; i < 4; i++) { float v = r[lane + 32 * i]; s += v * v; }
        #pragma unroll
        for (int o = 16; o; o >>= 1) s += __shfl_down_sync(0xffffffffu, s, o);
        if (lane == 0) g_xx[warp] = s;
    } else if (warp < BATCH + NCVS) {
        int rr = warp - BATCH;
        const float* r = C + (size_t)rr * FEAT;
        float s = 0.f;
        #pragma unroll
        for (int i = 0; i < 4; i++) { float v = r[lane + 32 * i]; s += v * v; }
        #pragma unroll
        for (int o = 16; o; o >>= 1) s += __shfl_down_sync(0xffffffffu, s, o);
        if (lane == 0) g_cc[rr] = s;
    }
}

// ---------------- K2: bf16 mma.sync distance GEMM + tile-min epilogue ----------------
#define SM_STRIDE 272
#define A_OFF 0
#define B_OFF (128 * SM_STRIDE)
#define GEMM_SMEM (2 * 128 * SM_STRIDE)

__device__ __forceinline__ uint32_t smem_u32(const void* p) {
    uint32_t a;
    asm("{ .reg .u64 t; cvta.to.shared.u64 t, %1; cvt.u32.u64 %0, t; }" : "=r"(a) : "l"(p));
    return a;
}
#define LDMX4(r0, r1, r2, r3, addr) \
    asm volatile("ldmatrix.sync.aligned.m8n8.x4.shared.b16 {%0,%1,%2,%3}, [%4];" \
                 : "=r"(r0), "=r"(r1), "=r"(r2), "=r"(r3) : "r"(addr))
#define MMA16816(c, a, b0, b1) \
    asm volatile("mma.sync.aligned.m16n8k16.row.col.f32.bf16.bf16.f32 " \
                 "{%0,%1,%2,%3}, {%4,%5,%6,%7}, {%8,%9}, {%0,%1,%2,%3};" \
                 : "+f"((c)[0]), "+f"((c)[1]), "+f"((c)[2]), "+f"((c)[3]) \
                 : "r"((a)[0]), "r"((a)[1]), "r"((a)[2]), "r"((a)[3]), "r"(b0), "r"(b1))

__global__ __launch_bounds__(256, 2) void gemm_tc_kernel() {
    extern __shared__ char dsm[];
    const int tid  = threadIdx.x;
    const int lane = tid & 31;
    const int w    = tid >> 5;
    const int bm   = blockIdx.y * 128;
    const int bn   = blockIdx.x * 128;
    const int wm   = (w & 3) * 32;
    const int wn   = (w >> 2) * 64;

    {
        const __nv_bfloat16* Asrc = g_xb + (size_t)bm * FEAT;
        const __nv_bfloat16* Bsrc = g_cb + (size_t)bn * FEAT;
        #pragma unroll
        for (int i = 0; i < 8; i++) {
            int idx = tid + i * 256;
            int r = idx >> 4, q = idx & 15;
            *(uint4*)(dsm + A_OFF + r * SM_STRIDE + q * 16) =
                *(const uint4*)(Asrc + (size_t)r * FEAT + q * 8);
            *(uint4*)(dsm + B_OFF + r * SM_STRIDE + q * 16) =
                *(const uint4*)(Bsrc + (size_t)r * FEAT + q * 8);
        }
    }
    __syncthreads();

    const uint32_t asb = smem_u32(dsm + A_OFF);
    const uint32_t bsb = smem_u32(dsm + B_OFF);
    const int tile = lane >> 3, rin = lane & 7;

    uint32_t aaddr[2], baddr[4];
    #pragma unroll
    for (int sm = 0; sm < 2; sm++)
        aaddr[sm] = asb + (uint32_t)((wm + sm * 16 + (tile & 1) * 8 + rin) * SM_STRIDE + (tile >> 1) * 16);
    #pragma unroll
    for (int np = 0; np < 4; np++)
        baddr[np] = bsb + (uint32_t)((wn + np * 16 + (tile & 1) * 8 + rin) * SM_STRIDE + (tile >> 1) * 16);

    float acc[2][8][4];
    #pragma unroll
    for (int s = 0; s < 2; s++)
        #pragma unroll
        for (int n = 0; n < 8; n++)
            #pragma unroll
            for (int q = 0; q < 4; q++) acc[s][n][q] = 0.f;

    #pragma unroll
    for (int ks = 0; ks < 8; ks++) {
        uint32_t a[2][4], bfr[4][4];
        LDMX4(a[0][0], a[0][1], a[0][2], a[0][3], aaddr[0] + ks * 32);
        LDMX4(a[1][0], a[1][1], a[1][2], a[1][3], aaddr[1] + ks * 32);
        #pragma unroll
        for (int np = 0; np < 4; np++)
            LDMX4(bfr[np][0], bfr[np][1], bfr[np][2], bfr[np][3], baddr[np] + ks * 32);
        #pragma unroll
        for (int s = 0; s < 2; s++)
            #pragma unroll
            for (int nt = 0; nt < 8; nt++) {
                int np = nt >> 1, odd = nt & 1;
                uint32_t b0 = odd ? bfr[np][1] : bfr[np][0];
                uint32_t b1 = odd ? bfr[np][3] : bfr[np][2];
                MMA16816(acc[s][nt], a[s], b0, b1);
            }
    }

    // epilogue: d2 = xx + cc - 2*dot, clamp >= 0; bf16 store + f32 tile minima
    const int cb = bn + wn + (lane & 3) * 2;
    #pragma unroll
    for (int s = 0; s < 2; s++) {
        int m0 = bm + wm + s * 16 + (lane >> 2);
        float xx0 = g_xx[m0], xx1 = g_xx[m0 + 8];
        __nv_bfloat16* row0 = g_d2b + (size_t)m0 * NCVS;
        __nv_bfloat16* row1 = g_d2b + (size_t)(m0 + 8) * NCVS;
        float mn0[2] = {1e30f, 1e30f}, mn1[2] = {1e30f, 1e30f};
        #pragma unroll
        for (int nt = 0; nt < 8; nt++) {
            int c = cb + nt * 8;
            float2 cc2 = *(const float2*)(g_cc + c);
            float2 o0, o1;
            o0.x = fmaxf(xx0 + cc2.x - 2.0f * acc[s][nt][0], 0.0f);
            o0.y = fmaxf(xx0 + cc2.y - 2.0f * acc[s][nt][1], 0.0f);
            o1.x = fmaxf(xx1 + cc2.x - 2.0f * acc[s][nt][2], 0.0f);
            o1.y = fmaxf(xx1 + cc2.y - 2.0f * acc[s][nt][3], 0.0f);
            *(__nv_bfloat162*)(row0 + c) = __float22bfloat162_rn(o0);
            *(__nv_bfloat162*)(row1 + c) = __float22bfloat162_rn(o1);
            int t = nt >> 2;
            mn0[t] = fminf(mn0[t], fminf(o0.x, o0.y));
            mn1[t] = fminf(mn1[t], fminf(o1.x, o1.y));
        }
        #pragma unroll
        for (int t = 0; t < 2; t++) {
            mn0[t] = fminf(mn0[t], __shfl_xor_sync(0xffffffffu, mn0[t], 1));
            mn0[t] = fminf(mn0[t], __shfl_xor_sync(0xffffffffu, mn0[t], 2));
            mn1[t] = fminf(mn1[t], __shfl_xor_sync(0xffffffffu, mn1[t], 1));
            mn1[t] = fminf(mn1[t], __shfl_xor_sync(0xffffffffu, mn1[t], 2));
            if ((lane & 3) == 0) {
                int gt = ((bn + wn) >> 5) + t;
                g_tmin[(size_t)m0 * NTILE + gt]       = mn0[t];
                g_tmin[(size_t)(m0 + 8) * NTILE + gt] = mn1[t];
            }
        }
    }
}

// ---------------- K3: tile-min pruned topk + exact rescore + fused scatter ----------
// tmin (f32, pre-rounding) guarantees: 15 f32 values <= T15 => exact e15 <=
// T15+0.6; top-15 j: stored_j <= exact_j + 0.6(GEMM) + 1.0(bf16 round) <=
// T15+2.2; its tile tmin <= T15+1.2. Margin T = T15 + 2.5 covers both tile
// qualification and value filter. Exact rescore + rank select as proven.
__global__ __launch_bounds__(256) void topk_kernel(const float* __restrict__ X,
                                                   const float* __restrict__ C) {
    __shared__ float s_tmin[NTILE];
    __shared__ float s_T;
    __shared__ int   s_qt[NTILE];
    __shared__ int   s_nqt;
    __shared__ int   s_cnt;
    __shared__ int   s_cand[CMAX];
    __shared__ float s_ed[CMAX];
    __shared__ int   s_knn[KNN];

    const int row  = blockIdx.x;
    const int tid  = threadIdx.x;
    const int lane = tid & 31, w = tid >> 5;

    if (tid == 0) { s_cnt = 0; s_nqt = 0; }
    if (tid < NTILE) s_tmin[tid] = g_tmin[(size_t)row * NTILE + tid];
    __syncthreads();

    // T15 = tile-min with rank 14 (lex tie-break by index => unique)
    if (tid < NTILE) {
        float mv = s_tmin[tid];
        int rank = 0;
        #pragma unroll 4
        for (int jj = 0; jj < NTILE; jj++) {
            float o = s_tmin[jj];
            rank += (o < mv || (o == mv && jj < tid)) ? 1 : 0;
        }
        if (rank == KNN - 1) s_T = mv;
    }
    __syncthreads();
    const float T = s_T + 2.5f;

    // qualifying tiles
    if (tid < NTILE && s_tmin[tid] < T) s_qt[atomicAdd(&s_nqt, 1)] = tid;
    __syncthreads();
    const int NQ = s_nqt;

    // scan qualifying tiles (bf16): warp covers 2 tiles, 16 words each
    const uint32_t* drow = (const uint32_t*)(g_d2b + (size_t)row * NCVS);
    {
        const int half = lane >> 4;      // 0/1: which of the warp's 2 tiles
        const int li   = lane & 15;      // word index within tile
        for (int q = w * 2; q < NQ; q += 16) {
            int qq = q + half;
            if (qq < NQ) {
                int t = s_qt[qq];
                uint32_t u = drow[t * 16 + li];
                float v0 = __uint_as_float(u << 16);          // low bf16 (exact)
                float v1 = __uint_as_float(u & 0xFFFF0000u);  // high bf16 (exact)
                int jb = t * 32 + li * 2;
                if (v0 < T) {
                    int p = atomicAdd(&s_cnt, 1);
                    if (p < CMAX) s_cand[p] = jb;
                }
                if (v1 < T) {
                    int p = atomicAdd(&s_cnt, 1);
                    if (p < CMAX) s_cand[p] = jb + 1;
                }
            }
        }
    }
    __syncthreads();
    const int M = (s_cnt < CMAX) ? s_cnt : CMAX;

    // exact f32 rescore: warp-per-candidate, coalesced (proven)
    {
        float4 xq = *(const float4*)(X + (size_t)row * FEAT + lane * 4);
        float xxv = g_xx[row];
        for (int c = w; c < M; c += 8) {
            int j = s_cand[c];
            float4 cq = *(const float4*)(C + (size_t)j * FEAT + lane * 4);
            float p = xq.x * cq.x + xq.y * cq.y + xq.z * cq.z + xq.w * cq.w;
            #pragma unroll
            for (int o = 16; o; o >>= 1) p += __shfl_down_sync(0xffffffffu, p, o);
            if (lane == 0) s_ed[c] = fmaxf(xxv + g_cc[j] - 2.0f * p, 0.0f);
        }
    }
    __syncthreads();

    // rank-based select: rank_c = #{keys < key_c}; rank < 15 writes knn[rank]
    for (int c = tid; c < M; c += 256) {
        unsigned long long key =
            ((unsigned long long)__float_as_uint(s_ed[c]) << 32) | (unsigned)s_cand[c];
        int rank = 0;
        for (int jj = 0; jj < M; jj++) {
            unsigned long long kj =
                ((unsigned long long)__float_as_uint(s_ed[jj]) << 32) | (unsigned)s_cand[jj];
            rank += (kj < key) ? 1 : 0;
        }
        if (rank < KNN) {
            s_knn[rank] = s_cand[c];
            g_knn[row * KNN + rank] = s_cand[c];
        }
    }
    __syncthreads();

    // fused scatter
    if (w == 0) {
        int closest = s_knn[0];
        if (lane == 0) atomicAdd(&g_visits[closest], 1);
        if (lane < KNN) atomicAdd(&g_cce[(size_t)closest * NCVS + s_knn[lane]], 1);
    }
}

// ---------------- K4: build per-label neighbor lists (lazy conn load) ---------------
// (0.9f)^10 < f32(double(0.9^10)) so integer-edge rows keep enc <= 9 only.
// conn[j] is loaded ONLY when the decay test already passed (~0.7% of j), cutting
// the conn stream from 64 MB to ~nothing.
__global__ void build_kernel(const float* __restrict__ edges, const float* __restrict__ conn) {
    __shared__ int s_scan[256];
    const int lab = blockIdx.x;
    const int tid = threadIdx.x;
    float vis = (float)g_visits[lab];
    const int4*   ccer = (const int4*)  (g_cce + (size_t)lab * NCVS);
    const float4* er   = (const float4*)(edges + (size_t)lab * NCVS);
    const float*  cor  = conn + (size_t)lab * NCVS;

    unsigned mask = 0;
    #pragma unroll
    for (int it = 0; it < 4; it++) {
        int g = tid + (it << 8);
        int4   c4 = ccer[g];
        float4 e4 = er[g];
        int    cc[4] = {c4.x, c4.y, c4.z, c4.w};
        float  ee[4] = {e4.x, e4.y, e4.z, e4.w};
        #pragma unroll
        for (int q = 0; q < 4; q++) {
            bool keep = false;
            if (cc[q] > 0 || ee[q] > 0.f) {
                float base = fmaxf(ee[q], (cc[q] > 0) ? 1.0f : 0.0f);
                float enc  = fmaxf(vis - (float)cc[q], 0.0f);
                if (base >= 1.0f) keep = (enc < 9.5f);
                else {
                    float en = base * __powf(0.89999997615814209f, enc);
                    keep = !(en < 0.34867844358f);
                }
                if (keep) keep = (cor[g * 4 + q] < 1.0f);   // lazy conn load
            }
            if (keep) mask |= (1u << (it * 4 + q));
        }
    }
    int cnt = __popc(mask);
    s_scan[tid] = cnt;
    __syncthreads();
    for (int off = 1; off < 256; off <<= 1) {
        int vv = (tid >= off) ? s_scan[tid - off] : 0;
        __syncthreads();
        s_scan[tid] += vv;
        __syncthreads();
    }
    int pos = s_scan[tid] - cnt;
    int* dst = g_nlist + (size_t)lab * NCVS;
    #pragma unroll
    for (int b = 0; b < 16; b++)
        if (mask & (1u << b)) dst[pos++] = 4 * (tid + ((b >> 2) << 8)) + (b & 3);
    if (tid == 255) g_ncnt[lab] = s_scan[255];
}

// ---------------- K5: per-sample loss, exact f32 neighbor distances ----------------
__global__ void loss_kernel(const float* __restrict__ X, const float* __restrict__ C,
                            const int* __restrict__ labels) {
    __shared__ float s_dp[4], s_se[4], s_sed[4];
    const int b    = blockIdx.x;
    const int tid  = threadIdx.x;
    const int lane = tid & 31, wid = tid >> 5;
    const int lab  = labels[b];

    const float* xr = X + (size_t)b   * FEAT;
    const float* cr = C + (size_t)lab * FEAT;
    float dlt = xr[tid] - cr[tid];
    float dp  = dlt * dlt;
    #pragma unroll
    for (int o = 16; o; o >>= 1) dp += __shfl_down_sync(0xffffffffu, dp, o);

    const int  L  = g_ncnt[lab];
    const int* nl = g_nlist + (size_t)lab * NCVS;
    const float xxv = g_xx[b];
    float4 xq = *(const float4*)(xr + lane * 4);

    float se = 0.f, sed = 0.f;
    for (int k = wid; k < L; k += 4) {
        int j = nl[k];
        float4 cq = *(const float4*)(C + (size_t)j * FEAT + lane * 4);
        float p = xq.x * cq.x + xq.y * cq.y + xq.z * cq.z + xq.w * cq.w;
        #pragma unroll
        for (int o = 16; o; o >>= 1) p += __shfl_down_sync(0xffffffffu, p, o);
        if (lane == 0) {
            float dd = fmaxf(xxv + g_cc[j] - 2.0f * p, 0.0f);
            if (dd > 0.f) {
                float ex = expf(-0.001f * dd);
                se  += ex;
                sed += ex * dd;
            }
        }
    }

    if (lane == 0) { s_dp[wid] = dp; s_se[wid] = se; s_sed[wid] = sed; }
    __syncthreads();
    if (tid == 0) {
        float dpt  = s_dp[0]  + s_dp[1]  + s_dp[2]  + s_dp[3];
        float set  = s_se[0]  + s_se[1]  + s_se[2]  + s_se[3];
        float sedt = s_sed[0] + s_sed[1] + s_sed[2] + s_sed[3];
        float wsum = (set > 0.f) ? (sedt / set) : 0.f;   // nan -> 0 branch
        float mu = dpt - wsum;
        if (mu > 0.f) atomicAdd(&g_loss, (double)mu);
    }
}

// ---------------- K6: finalize ----------------
__global__ void finalize_kernel(float* out) {
    if (threadIdx.x == 0) out[0] = (float)(g_loss * (1.0 / (double)BATCH));
}

// ---------------- K7: undo scatter (self-cleaning state) ----------------
__global__ void undo_kernel() {
    int b = blockIdx.x * blockDim.x + threadIdx.x;
    if (b == 0) g_loss = 0.0;
    if (b >= BATCH) return;
    int closest = g_knn[b * KNN];
    atomicSub(&g_visits[closest], 1);
    #pragma unroll
    for (int k = 0; k < KNN; k++)
        atomicSub(&g_cce[(size_t)closest * NCVS + g_knn[b * KNN + k]], 1);
}

// ---------------- launch ----------------
extern "C" void kernel_launch(void* const* d_in, const int* in_sizes, int n_in,
                              void* d_out, int out_size) {
    const float* x      = (const float*)d_in[0];
    const float* cvs    = (const float*)d_in[1];
    const float* edges  = (const float*)d_in[2];
    const float* conn   = (const float*)d_in[3];
    const int*   labels = (const int*)d_in[4];
    float* out = (float*)d_out;

    cudaFuncSetAttribute(gemm_tc_kernel, cudaFuncAttributeMaxDynamicSharedMemorySize, GEMM_SMEM);

    split_kernel<<<(BATCH + NCVS) * FEAT / 256, 256>>>(x, cvs);
    norms_kernel<<<(BATCH + NCVS) / 8, 256>>>(x, cvs);
    gemm_tc_kernel<<<dim3(NCVS / 128, BATCH / 128), 256, GEMM_SMEM>>>();
    topk_kernel<<<BATCH, 256>>>(x, cvs);
    build_kernel<<<NCVS, 256>>>(edges, conn);
    loss_kernel<<<BATCH, 128>>>(x, cvs, labels);
    finalize_kernel<<<1, 32>>>(out);
    undo_kernel<<<BATCH / 256, 256>>>();
}